// round 4
// baseline (speedup 1.0000x reference)
#include <cuda_runtime.h>
#include <math.h>

#define KTOK 2048
#define DDIM 2048
#define NBATCH 16
#define MAXIT 50
#define EPSF 1e-8f
#define STEPSZ (0.1f / 2048.0f)

#define NBLK 128
#define NTHR 256
#define NWARP 8
#define ROWS 16                 // tokens per CTA
#define RPW 2                   // rows per warp
#define DPT (DDIM / NTHR)       // 8 scalar d per thread
#define DSL (DDIM / NBLK)       // 16 scalar d per CTA slice
#define D4  (DDIM / 4)          // 512 float4
#define D4PT (D4 / NTHR)        // 2 float4 per thread

#define SMEM_FLOATS (ROWS * DDIM + DDIM + 32 + 64)
#define SMEM_BYTES (SMEM_FLOATS * 4)

// ---------------- global scratch (zeroed-on-exit invariant) ----------------
__device__ float g_m[DDIM];
__device__ float g_grad[3][DDIM];
__device__ float g_slam[3];
__device__ float g_viol;
__device__ unsigned g_flags[NBLK];
__device__ unsigned g_gen;

// ---------------- relaxed gpu-scope ld/st for barrier words ----------------
__device__ __forceinline__ unsigned ld_rlx(const unsigned *p)
{
    unsigned v;
    asm volatile("ld.relaxed.gpu.b32 %0, [%1];" : "=r"(v) : "l"(p) : "memory");
    return v;
}
__device__ __forceinline__ void st_rlx(unsigned *p, unsigned v)
{
    asm volatile("st.relaxed.gpu.b32 [%0], %1;" :: "l"(p), "r"(v) : "memory");
}

// ---------------- grid barrier: flag array + gen broadcast ----------------
__device__ __forceinline__ void grid_bar(unsigned phase)
{
    __threadfence();                       // release all threads' prior writes
    __syncthreads();
    if (blockIdx.x == 0) {
        if (threadIdx.x < NBLK && threadIdx.x != 0) {
            while (ld_rlx(&g_flags[threadIdx.x]) < phase) __nanosleep(32);
        }
        __syncthreads();
        if (threadIdx.x == 0) { __threadfence(); st_rlx(&g_gen, phase); }
    } else {
        if (threadIdx.x == 0) {
            st_rlx(&g_flags[blockIdx.x], phase);
            while (ld_rlx(&g_gen) < phase) __nanosleep(32);
        }
    }
    __syncthreads();
    __threadfence();                       // acquire
}

// deterministic block-wide pair sum: identical on every thread & CTA
__device__ __forceinline__ void block_sum2(float a, float b, float *red,
                                           float &oa, float &ob)
{
#pragma unroll
    for (int o = 16; o > 0; o >>= 1) {
        a += __shfl_down_sync(0xffffffffu, a, o);
        b += __shfl_down_sync(0xffffffffu, b, o);
    }
    __syncthreads();
    if ((threadIdx.x & 31) == 0) {
        red[threadIdx.x >> 5] = a;
        red[8 + (threadIdx.x >> 5)] = b;
    }
    __syncthreads();
    float sa = red[0], sb = red[8];
#pragma unroll
    for (int i = 1; i < NWARP; i++) { sa += red[i]; sb += red[8 + i]; }
    __syncthreads();
    oa = sa; ob = sb;
}

__device__ __forceinline__ float block_sum1(float v, float *red)
{
#pragma unroll
    for (int o = 16; o > 0; o >>= 1) v += __shfl_down_sync(0xffffffffu, v, o);
    __syncthreads();
    if ((threadIdx.x & 31) == 0) red[threadIdx.x >> 5] = v;
    __syncthreads();
    float s = red[0];
#pragma unroll
    for (int i = 1; i < NWARP; i++) s += red[i];
    __syncthreads();
    return s;
}

// log_map_at coefficients: v_k = -lam*p + mu*x_k (scalars only)
__device__ __forceinline__ void lam_mu(float dot, float xs, float p_sq,
                                       float &lam, float &mu)
{
    const float xy  = -dot;
    const float xsc = fminf(p_sq, 0.99f);
    const float ysc = fminf(xs, 0.99f);
    const float a   = 1.0f + 2.0f * xy + ysc;
    const float b   = 1.0f - xsc;
    const float den = fmaxf(1.0f + 2.0f * xy + xsc * ysc, EPSF);
    const float numsq = fmaxf(a * a * p_sq + b * b * xs - 2.0f * a * b * dot, 0.0f);
    const float rn  = sqrtf(numsq) / den;
    const float maxn = 1.0f - EPSF;
    const float c   = (rn >= maxn) ? (maxn - EPSF) / rn : 1.0f;
    const float n   = rn * c;
    const float s   = fminf(n, 1.0f - EPSF);
    const float scale = 2.0f * atanhf(s) / (n + EPSF);
    const float t   = (n < EPSF) ? 0.0f : scale * c / den;
    lam = t * a;
    mu  = t * b;
}

__global__ void __launch_bounds__(NTHR, 1)
traj_kernel(const float *__restrict__ in, float *__restrict__ out)
{
    extern __shared__ float smem[];
    float *Xs  = smem;                 // [ROWS][DDIM]
    float *Ps  = Xs + ROWS * DDIM;     // [DDIM] redundant center
    float *red = Ps + DDIM;            // [32]
    float *aux = red + 32;             // [64]: [0..15]=xsq, [16..31]=w0, [32..47]=mu

    const int tid  = threadIdx.x;
    const int blk  = blockIdx.x;
    const int lane = tid & 31;
    const int w    = tid >> 5;
    const int ds   = blk * DSL;

    const unsigned base = ld_rlx(&g_gen);   // stable until first barrier
    unsigned cnt = 0;

    // ---- load tokens: X[k,:] = mean_b in[k,b,:]; xsq per row ----
    const float inv_b = 1.0f / (float)NBATCH;
    {
        const int r = w * RPW;             // this warp's first row
#pragma unroll
        for (int rr = 0; rr < RPW; rr++) {
            const int k = blk * ROWS + r + rr;
            const float4 *src = (const float4 *)(in + (size_t)k * NBATCH * DDIM);
            float4 *dst = (float4 *)(Xs + (r + rr) * DDIM);
            float ss = 0.0f;
            for (int j = 0; j < 16; j += 2) {       // 2 d4 in flight -> 32 LDG
                const int dA = lane + j * 32;
                const int dB = dA + 32;
                float4 a = make_float4(0.f, 0.f, 0.f, 0.f);
                float4 c = make_float4(0.f, 0.f, 0.f, 0.f);
#pragma unroll
                for (int b = 0; b < NBATCH; b++) {
                    float4 t = src[b * D4 + dA];
                    float4 u = src[b * D4 + dB];
                    a.x += t.x; a.y += t.y; a.z += t.z; a.w += t.w;
                    c.x += u.x; c.y += u.y; c.z += u.z; c.w += u.w;
                }
                a.x *= inv_b; a.y *= inv_b; a.z *= inv_b; a.w *= inv_b;
                c.x *= inv_b; c.y *= inv_b; c.z *= inv_b; c.w *= inv_b;
                dst[dA] = a; dst[dB] = c;
                ss += a.x * a.x + a.y * a.y + a.z * a.z + a.w * a.w;
                ss += c.x * c.x + c.y * c.y + c.z * c.z + c.w * c.w;
            }
#pragma unroll
            for (int o = 16; o > 0; o >>= 1)
                ss += __shfl_down_sync(0xffffffffu, ss, o);
            if (lane == 0) aux[r + rr] = ss;
        }
    }
    __syncthreads();

    // w0_k = log_map0 scale / K
    if (tid < ROWS) {
        const float xs = aux[tid];
        const float n  = sqrtf(xs);
        const float s  = fminf(n, 1.0f - EPSF);
        const float sc = (n < EPSF) ? 0.0f : atanhf(s) / (n + EPSF);
        aux[16 + tid] = sc * (1.0f / (float)KTOK);
    }
    __syncthreads();

    // ---- m partial: g_m += sum_r w0_r * X[r,:]  (g_m zero on entry) ----
    {
        const float4 *Xs4 = (const float4 *)Xs;
#pragma unroll
        for (int j = 0; j < D4PT; j++) {
            const int d4 = tid + j * NTHR;
            float4 acc = make_float4(0.f, 0.f, 0.f, 0.f);
#pragma unroll
            for (int r = 0; r < ROWS; r++) {
                const float wr = aux[16 + r];
                float4 x = Xs4[r * D4 + d4];
                acc.x += wr * x.x; acc.y += wr * x.y;
                acc.z += wr * x.z; acc.w += wr * x.w;
            }
            atomicAdd(&g_m[4 * d4 + 0], acc.x);
            atomicAdd(&g_m[4 * d4 + 1], acc.y);
            atomicAdd(&g_m[4 * d4 + 2], acc.z);
            atomicAdd(&g_m[4 * d4 + 3], acc.w);
        }
    }

    grid_bar(base + ++cnt);            // barrier A: m complete

    // ---- p0 = exp_map0(m), redundant per CTA ----
    float p_sq;
    {
        float part = 0.0f, ml[DPT];
#pragma unroll
        for (int j = 0; j < DPT; j++) {
            ml[j] = __ldcg(&g_m[tid + j * NTHR]);
            part += ml[j] * ml[j];
        }
        const float msq = block_sum1(part, red);
        const float n   = sqrtf(msq);
        const float sc  = (n < EPSF) ? 0.0f : tanhf(n) / (n + EPSF);
#pragma unroll
        for (int j = 0; j < DPT; j++) Ps[tid + j * NTHR] = sc * ml[j];
        p_sq = sc * sc * msq;
        __syncthreads();
    }

    // =================== Karcher loop: 1 barrier per iteration ===========
    for (int it = 0; it < MAXIT; it++) {
        const int b  = it % 3;
        const int nb = (it + 1) % 3;

        // -- phase 1: zero next buffer, dots, lam/mu, accumulate grad --
        if (tid < DSL) g_grad[nb][ds + tid] = 0.0f;
        if (blk == 0 && tid == 0) g_slam[nb] = 0.0f;

        {
            const int r0 = w * RPW;
            const float4 *x0 = (const float4 *)(Xs + r0 * DDIM);
            const float4 *x1 = (const float4 *)(Xs + (r0 + 1) * DDIM);
            const float4 *pp = (const float4 *)Ps;
            float s0a = 0.f, s0b = 0.f, s1a = 0.f, s1b = 0.f;
#pragma unroll
            for (int j = 0; j < 16; j++) {
                const int d4 = lane + j * 32;
                float4 p = pp[d4];
                float4 a = x0[d4];
                float4 c = x1[d4];
                s0a += a.x * p.x + a.y * p.y;
                s0b += a.z * p.z + a.w * p.w;
                s1a += c.x * p.x + c.y * p.y;
                s1b += c.z * p.z + c.w * p.w;
            }
            float s0 = s0a + s0b, s1 = s1a + s1b;
#pragma unroll
            for (int o = 16; o > 0; o >>= 1) {
                s0 += __shfl_down_sync(0xffffffffu, s0, o);
                s1 += __shfl_down_sync(0xffffffffu, s1, o);
            }
            if (lane == 0) {
                float l0, m0, l1, m1;
                lam_mu(s0, aux[r0], p_sq, l0, m0);
                lam_mu(s1, aux[r0 + 1], p_sq, l1, m1);
                aux[32 + r0] = m0;
                aux[32 + r0 + 1] = m1;
                atomicAdd(&g_slam[b], l0 + l1);
            }
        }
        __syncthreads();               // mu visible

        {
            const float4 *Xs4 = (const float4 *)Xs;
#pragma unroll
            for (int j = 0; j < D4PT; j++) {
                const int d4 = tid + j * NTHR;
                float4 acc = make_float4(0.f, 0.f, 0.f, 0.f);
#pragma unroll
                for (int r = 0; r < ROWS; r++) {
                    const float mr = aux[32 + r];
                    float4 x = Xs4[r * D4 + d4];
                    acc.x += mr * x.x; acc.y += mr * x.y;
                    acc.z += mr * x.z; acc.w += mr * x.w;
                }
                atomicAdd(&g_grad[b][4 * d4 + 0], acc.x);
                atomicAdd(&g_grad[b][4 * d4 + 1], acc.y);
                atomicAdd(&g_grad[b][4 * d4 + 2], acc.z);
                atomicAdd(&g_grad[b][4 * d4 + 3], acc.w);
            }
        }

        grid_bar(base + ++cnt);        // grad[b] complete chip-wide

        // -- phase 2: redundant p update per CTA --
        if (it == 0 && tid < DSL) g_m[ds + tid] = 0.0f;   // exit invariant

        const float slam = __ldcg(&g_slam[b]);
        float gl[DPT], a1 = 0.0f, a2 = 0.0f;
#pragma unroll
        for (int j = 0; j < DPT; j++) {
            const int d = tid + j * NTHR;
            const float g = __ldcg(&g_grad[b][d]) - Ps[d] * slam;
            gl[j] = g;
            a1 += g * g;
            a2 += Ps[d] * g;
        }
        float gg, pg;
        block_sum2(a1, a2, red, gg, pg);

        const float n_v = STEPSZ * sqrtf(gg);
        if (n_v >= EPSF) {
            const float sc  = tanhf(0.5f * n_v) / (n_v + EPSF);
            const float xy  = -STEPSZ * sc * pg;
            const float ysq = STEPSZ * STEPSZ * sc * sc * gg;
            const float xsc = fminf(p_sq, 0.99f);
            const float ysc = fminf(ysq, 0.99f);
            const float A   = 1.0f + 2.0f * xy + ysc;
            const float B   = 1.0f - xsc;
            const float dn  = fmaxf(1.0f + 2.0f * xy + xsc * ysc, EPSF);
            const float ca  = A / dn;
            const float cb  = (-STEPSZ * sc) * B / dn;
            float pp = 0.0f;
#pragma unroll
            for (int j = 0; j < DPT; j++) {
                const int d = tid + j * NTHR;
                const float nv = ca * Ps[d] + cb * gl[j];
                Ps[d] = nv;
                pp += nv * nv;
            }
            float rsq = block_sum1(pp, red);
            const float rn = sqrtf(rsq);
            if (rn >= 1.0f - EPSF) {
                const float cf = (1.0f - 2.0f * EPSF) / rn;
#pragma unroll
                for (int j = 0; j < DPT; j++) Ps[tid + j * NTHR] *= cf;
                rsq *= cf * cf;
            }
            p_sq = rsq;
        }
        __syncthreads();
    }

    // ---- final distances + violation (uses CTA-local Ps) ----
    {
        const int r0 = w * RPW;
        const float4 *x0 = (const float4 *)(Xs + r0 * DDIM);
        const float4 *x1 = (const float4 *)(Xs + (r0 + 1) * DDIM);
        const float4 *pp = (const float4 *)Ps;
        float s0 = 0.f, s1 = 0.f;
#pragma unroll
        for (int j = 0; j < 16; j++) {
            const int d4 = lane + j * 32;
            float4 p = pp[d4];
            float4 a = x0[d4];
            float4 c = x1[d4];
            s0 += a.x * p.x + a.y * p.y + a.z * p.z + a.w * p.w;
            s1 += c.x * p.x + c.y * p.y + c.z * p.z + c.w * p.w;
        }
#pragma unroll
        for (int o = 16; o > 0; o >>= 1) {
            s0 += __shfl_down_sync(0xffffffffu, s0, o);
            s1 += __shfl_down_sync(0xffffffffu, s1, o);
        }
        if (lane == 0) {
            float vi = 0.0f;
#pragma unroll
            for (int q = 0; q < 2; q++) {
                const float xs  = aux[r0 + q];
                const float dot = q ? s1 : s0;
                const float dsq = xs - 2.0f * dot + p_sq;
                const float den = fmaxf((1.0f - xs) * (1.0f - p_sq), EPSF);
                const float fr  = fmaxf(dsq / den, 0.0f);
                vi += fmaxf(asinhf(sqrtf(fr)) - 2.0f, 0.0f);
            }
            atomicAdd(&g_viol, vi);
        }
    }

    grid_bar(base + ++cnt);            // final barrier

    // ---- restore zeroed-on-exit invariant + emit output ----
    if (tid < DSL) {
        g_grad[0][ds + tid] = 0.0f;    // dirty from iter 48
        g_grad[1][ds + tid] = 0.0f;    // dirty from iter 49
    }
    if (blk == 0 && tid == 0) {
        const float v = __ldcg(&g_viol);
        out[0] = v * (1.0f / (float)KTOK);
        g_viol = 0.0f;
        g_slam[0] = 0.0f;
        g_slam[1] = 0.0f;
    }
}

extern "C" void kernel_launch(void* const* d_in, const int* in_sizes, int n_in,
                              void* d_out, int out_size)
{
    (void)in_sizes; (void)n_in; (void)out_size;
    cudaFuncSetAttribute(traj_kernel,
                         cudaFuncAttributeMaxDynamicSharedMemorySize, SMEM_BYTES);
    const float *in = (const float *)d_in[0];
    float *out = (float *)d_out;
    traj_kernel<<<NBLK, NTHR, SMEM_BYTES>>>(in, out);
}

// round 5
// speedup vs baseline: 1.0092x; 1.0092x over previous
#include <cuda_runtime.h>
#include <math.h>

#define KTOK 2048
#define DDIM 2048
#define NBATCH 16
#define MAXIT 50
#define EPSF 1e-8f
#define STEPSZ (0.1f / 2048.0f)

#define NBLK 128
#define NTHR 256
#define NWARP 8
#define ROWS 16                 // tokens per CTA
#define RPW 2                   // rows per warp
#define DPT (DDIM / NTHR)       // 8 scalar d per thread
#define DSL (DDIM / NBLK)       // 16 scalar d per CTA slice
#define D4  (DDIM / 4)          // 512 float4
#define D4PT (D4 / NTHR)        // 2 float4 per thread

#define SMEM_FLOATS (ROWS * DDIM + DDIM + 32 + 64)
#define SMEM_BYTES (SMEM_FLOATS * 4)

// ---------------- global scratch ----------------
__device__ float g_m[DDIM];
__device__ float g_grad[2][DDIM];
__device__ float g_slam[2];
__device__ float g_viol;
__device__ unsigned g_cnt;          // monotonic barrier counter

__device__ __forceinline__ unsigned ld_rlx(const unsigned *p)
{
    unsigned v;
    asm volatile("ld.relaxed.gpu.b32 %0, [%1];" : "=r"(v) : "l"(p) : "memory");
    return v;
}

// grid barrier: single RED arrive + relaxed poll; fence by one thread only
// (canonical cooperative-groups grid.sync pattern)
__device__ __forceinline__ void grid_bar(unsigned target)
{
    __syncthreads();
    if (threadIdx.x == 0) {
        __threadfence();                  // release (block writes ordered by bar.sync)
        atomicAdd(&g_cnt, 1u);
        while (ld_rlx(&g_cnt) < target) {}
        __threadfence();                  // acquire
    }
    __syncthreads();
}

// deterministic block-wide sums
__device__ __forceinline__ void block_sum2(float a, float b, float *red,
                                           float &oa, float &ob)
{
#pragma unroll
    for (int o = 16; o > 0; o >>= 1) {
        a += __shfl_down_sync(0xffffffffu, a, o);
        b += __shfl_down_sync(0xffffffffu, b, o);
    }
    __syncthreads();
    if ((threadIdx.x & 31) == 0) {
        red[threadIdx.x >> 5] = a;
        red[8 + (threadIdx.x >> 5)] = b;
    }
    __syncthreads();
    float sa = red[0], sb = red[8];
#pragma unroll
    for (int i = 1; i < NWARP; i++) { sa += red[i]; sb += red[8 + i]; }
    __syncthreads();
    oa = sa; ob = sb;
}

__device__ __forceinline__ float block_sum1(float v, float *red)
{
#pragma unroll
    for (int o = 16; o > 0; o >>= 1) v += __shfl_down_sync(0xffffffffu, v, o);
    __syncthreads();
    if ((threadIdx.x & 31) == 0) red[threadIdx.x >> 5] = v;
    __syncthreads();
    float s = red[0];
#pragma unroll
    for (int i = 1; i < NWARP; i++) s += red[i];
    __syncthreads();
    return s;
}

// log_map_at coefficients: v_k = -lam*p + mu*x_k (scalars only)
__device__ __forceinline__ void lam_mu(float dot, float xs, float p_sq,
                                       float &lam, float &mu)
{
    const float xy  = -dot;
    const float xsc = fminf(p_sq, 0.99f);
    const float ysc = fminf(xs, 0.99f);
    const float a   = 1.0f + 2.0f * xy + ysc;
    const float b   = 1.0f - xsc;
    const float den = fmaxf(1.0f + 2.0f * xy + xsc * ysc, EPSF);
    const float numsq = fmaxf(a * a * p_sq + b * b * xs - 2.0f * a * b * dot, 0.0f);
    const float rn  = sqrtf(numsq) / den;
    const float maxn = 1.0f - EPSF;
    const float c   = (rn >= maxn) ? (maxn - EPSF) / rn : 1.0f;
    const float n   = rn * c;
    const float s   = fminf(n, 1.0f - EPSF);
    const float scale = 2.0f * atanhf(s) / (n + EPSF);
    const float t   = (n < EPSF) ? 0.0f : scale * c / den;
    lam = t * a;
    mu  = t * b;
}

__global__ void __launch_bounds__(NTHR, 1)
traj_kernel(const float *__restrict__ in, float *__restrict__ out)
{
    extern __shared__ float smem[];
    float *Xs  = smem;                 // [ROWS][DDIM]
    float *Ps  = Xs + ROWS * DDIM;     // [DDIM] redundant center
    float *red = Ps + DDIM;            // [32]
    float *aux = red + 32;             // [0..15]=xsq [16..31]=w0 [32..47]=mu [48..55]=warp scratch
    __shared__ unsigned s_base;

    const int tid  = threadIdx.x;
    const int blk  = blockIdx.x;
    const int lane = tid & 31;
    const int w    = tid >> 5;
    const int ds   = blk * DSL;

    if (tid == 0) s_base = ld_rlx(&g_cnt);   // stable between launches
    // ---- zero global scratch slices ----
    if (tid < DSL) {
        g_m[ds + tid] = 0.0f;
        g_grad[0][ds + tid] = 0.0f;
        g_grad[1][ds + tid] = 0.0f;
    }
    if (blk == 0 && tid == 0) { g_viol = 0.0f; g_slam[0] = 0.0f; g_slam[1] = 0.0f; }

    // ---- load tokens: X[k,:] = mean_b in[k,b,:]; xsq per row ----
    const float inv_b = 1.0f / (float)NBATCH;
    {
        const int r = w * RPW;
#pragma unroll
        for (int rr = 0; rr < RPW; rr++) {
            const int k = blk * ROWS + r + rr;
            const float4 *src = (const float4 *)(in + (size_t)k * NBATCH * DDIM);
            float4 *dst = (float4 *)(Xs + (r + rr) * DDIM);
            float ss = 0.0f;
            for (int j = 0; j < 16; j += 2) {       // 32 LDG.128 in flight
                const int dA = lane + j * 32;
                const int dB = dA + 32;
                float4 a = make_float4(0.f, 0.f, 0.f, 0.f);
                float4 c = make_float4(0.f, 0.f, 0.f, 0.f);
#pragma unroll
                for (int b = 0; b < NBATCH; b++) {
                    float4 t = src[b * D4 + dA];
                    float4 u = src[b * D4 + dB];
                    a.x += t.x; a.y += t.y; a.z += t.z; a.w += t.w;
                    c.x += u.x; c.y += u.y; c.z += u.z; c.w += u.w;
                }
                a.x *= inv_b; a.y *= inv_b; a.z *= inv_b; a.w *= inv_b;
                c.x *= inv_b; c.y *= inv_b; c.z *= inv_b; c.w *= inv_b;
                dst[dA] = a; dst[dB] = c;
                ss += a.x * a.x + a.y * a.y + a.z * a.z + a.w * a.w;
                ss += c.x * c.x + c.y * c.y + c.z * c.z + c.w * c.w;
            }
#pragma unroll
            for (int o = 16; o > 0; o >>= 1)
                ss += __shfl_down_sync(0xffffffffu, ss, o);
            if (lane == 0) aux[r + rr] = ss;
        }
    }
    __syncthreads();

    // w0_k = log_map0 scale / K
    if (tid < ROWS) {
        const float xs = aux[tid];
        const float n  = sqrtf(xs);
        const float s  = fminf(n, 1.0f - EPSF);
        const float sc = (n < EPSF) ? 0.0f : atanhf(s) / (n + EPSF);
        aux[16 + tid] = sc * (1.0f / (float)KTOK);
    }
    __syncthreads();

    unsigned cnt = 0;
    const unsigned base = s_base;
    grid_bar(base + (++cnt) * NBLK);   // zeroing complete chip-wide

    // ---- m partial: g_m += sum_r w0_r * X[r,:] ----
    {
        const float4 *Xs4 = (const float4 *)Xs;
#pragma unroll
        for (int j = 0; j < D4PT; j++) {
            const int d4 = tid + j * NTHR;
            float4 acc = make_float4(0.f, 0.f, 0.f, 0.f);
#pragma unroll
            for (int r = 0; r < ROWS; r++) {
                const float wr = aux[16 + r];
                float4 x = Xs4[r * D4 + d4];
                acc.x += wr * x.x; acc.y += wr * x.y;
                acc.z += wr * x.z; acc.w += wr * x.w;
            }
            atomicAdd(&g_m[4 * d4 + 0], acc.x);
            atomicAdd(&g_m[4 * d4 + 1], acc.y);
            atomicAdd(&g_m[4 * d4 + 2], acc.z);
            atomicAdd(&g_m[4 * d4 + 3], acc.w);
        }
    }

    grid_bar(base + (++cnt) * NBLK);   // m complete

    // ---- p0 = exp_map0(m), redundant per CTA ----
    float p_sq;
    {
        float part = 0.0f, ml[DPT];
#pragma unroll
        for (int j = 0; j < DPT; j++) {
            ml[j] = __ldcg(&g_m[tid + j * NTHR]);
            part += ml[j] * ml[j];
        }
        const float msq = block_sum1(part, red);
        const float n   = sqrtf(msq);
        const float sc  = (n < EPSF) ? 0.0f : tanhf(n) / (n + EPSF);
#pragma unroll
        for (int j = 0; j < DPT; j++) Ps[tid + j * NTHR] = sc * ml[j];
        p_sq = sc * sc * msq;
        __syncthreads();
    }

    // =================== Karcher loop: 2 barriers / iter ===================
    for (int it = 0; it < MAXIT; it++) {
        const int b = it & 1, nb = b ^ 1;

        // -- phase 1: float4 dots, lam/mu, single-atomic slam, grad atomics --
        {
            const int r0 = w * RPW;
            const float4 *x0 = (const float4 *)(Xs + r0 * DDIM);
            const float4 *x1 = (const float4 *)(Xs + (r0 + 1) * DDIM);
            const float4 *pp = (const float4 *)Ps;
            float s0a = 0.f, s0b = 0.f, s1a = 0.f, s1b = 0.f;
#pragma unroll
            for (int j = 0; j < 16; j++) {
                const int d4 = lane + j * 32;
                float4 p = pp[d4];
                float4 a = x0[d4];
                float4 c = x1[d4];
                s0a += a.x * p.x + a.y * p.y;
                s0b += a.z * p.z + a.w * p.w;
                s1a += c.x * p.x + c.y * p.y;
                s1b += c.z * p.z + c.w * p.w;
            }
            float s0 = s0a + s0b, s1 = s1a + s1b;
#pragma unroll
            for (int o = 16; o > 0; o >>= 1) {
                s0 += __shfl_down_sync(0xffffffffu, s0, o);
                s1 += __shfl_down_sync(0xffffffffu, s1, o);
            }
            if (lane == 0) {
                float l0, m0, l1, m1;
                lam_mu(s0, aux[r0], p_sq, l0, m0);
                lam_mu(s1, aux[r0 + 1], p_sq, l1, m1);
                aux[32 + r0] = m0;
                aux[32 + r0 + 1] = m1;
                aux[48 + w] = l0 + l1;
            }
        }
        __syncthreads();               // mu + lam partials visible
        if (tid == 0) {
            float sl = aux[48];
#pragma unroll
            for (int i = 1; i < NWARP; i++) sl += aux[48 + i];
            atomicAdd(&g_slam[b], sl);
        }

        {
            const float4 *Xs4 = (const float4 *)Xs;
#pragma unroll
            for (int j = 0; j < D4PT; j++) {
                const int d4 = tid + j * NTHR;
                float4 acc = make_float4(0.f, 0.f, 0.f, 0.f);
#pragma unroll
                for (int r = 0; r < ROWS; r++) {
                    const float mr = aux[32 + r];
                    float4 x = Xs4[r * D4 + d4];
                    acc.x += mr * x.x; acc.y += mr * x.y;
                    acc.z += mr * x.z; acc.w += mr * x.w;
                }
                atomicAdd(&g_grad[b][4 * d4 + 0], acc.x);
                atomicAdd(&g_grad[b][4 * d4 + 1], acc.y);
                atomicAdd(&g_grad[b][4 * d4 + 2], acc.z);
                atomicAdd(&g_grad[b][4 * d4 + 3], acc.w);
            }
        }

        grid_bar(base + (++cnt) * NBLK);   // grad[b] complete

        // -- phase 2: redundant p update; zero next buffer --
        const float slam = __ldcg(&g_slam[b]);
        float gl[DPT], a1 = 0.0f, a2 = 0.0f;
#pragma unroll
        for (int j = 0; j < DPT; j++) {
            const int d = tid + j * NTHR;
            const float g = __ldcg(&g_grad[b][d]) - Ps[d] * slam;
            gl[j] = g;
            a1 += g * g;
            a2 += Ps[d] * g;
        }
        float gg, pg;
        block_sum2(a1, a2, red, gg, pg);

        if (tid < DSL) g_grad[nb][ds + tid] = 0.0f;
        if (blk == 0 && tid == 0) g_slam[nb] = 0.0f;

        const float n_v = STEPSZ * sqrtf(gg);
        if (n_v >= EPSF) {
            const float sc  = tanhf(0.5f * n_v) / (n_v + EPSF);
            const float xy  = -STEPSZ * sc * pg;
            const float ysq = STEPSZ * STEPSZ * sc * sc * gg;
            const float xsc = fminf(p_sq, 0.99f);
            const float ysc = fminf(ysq, 0.99f);
            const float A   = 1.0f + 2.0f * xy + ysc;
            const float B   = 1.0f - xsc;
            const float dn  = fmaxf(1.0f + 2.0f * xy + xsc * ysc, EPSF);
            const float ca  = A / dn;
            const float cb  = (-STEPSZ * sc) * B / dn;
            float pp = 0.0f;
#pragma unroll
            for (int j = 0; j < DPT; j++) {
                const int d = tid + j * NTHR;
                const float nv = ca * Ps[d] + cb * gl[j];
                Ps[d] = nv;
                pp += nv * nv;
            }
            float rsq = block_sum1(pp, red);
            const float rn = sqrtf(rsq);
            if (rn >= 1.0f - EPSF) {
                const float cf = (1.0f - 2.0f * EPSF) / rn;
#pragma unroll
                for (int j = 0; j < DPT; j++) Ps[tid + j * NTHR] *= cf;
                rsq *= cf * cf;
            }
            p_sq = rsq;
        }
        __syncthreads();

        grid_bar(base + (++cnt) * NBLK);   // update + zeroing settled
    }

    // ---- final distances + violation (CTA-local Ps) ----
    {
        const int r0 = w * RPW;
        const float4 *x0 = (const float4 *)(Xs + r0 * DDIM);
        const float4 *x1 = (const float4 *)(Xs + (r0 + 1) * DDIM);
        const float4 *pp = (const float4 *)Ps;
        float s0 = 0.f, s1 = 0.f;
#pragma unroll
        for (int j = 0; j < 16; j++) {
            const int d4 = lane + j * 32;
            float4 p = pp[d4];
            float4 a = x0[d4];
            float4 c = x1[d4];
            s0 += a.x * p.x + a.y * p.y + a.z * p.z + a.w * p.w;
            s1 += c.x * p.x + c.y * p.y + c.z * p.z + c.w * p.w;
        }
#pragma unroll
        for (int o = 16; o > 0; o >>= 1) {
            s0 += __shfl_down_sync(0xffffffffu, s0, o);
            s1 += __shfl_down_sync(0xffffffffu, s1, o);
        }
        if (lane == 0) {
            float vi = 0.0f;
#pragma unroll
            for (int q = 0; q < 2; q++) {
                const float xs  = aux[r0 + q];
                const float dot = q ? s1 : s0;
                const float dsq = xs - 2.0f * dot + p_sq;
                const float den = fmaxf((1.0f - xs) * (1.0f - p_sq), EPSF);
                const float fr  = fmaxf(dsq / den, 0.0f);
                vi += fmaxf(asinhf(sqrtf(fr)) - 2.0f, 0.0f);
            }
            aux[48 + w] = vi;
        }
    }
    __syncthreads();
    if (tid == 0) {
        float vi = aux[48];
#pragma unroll
        for (int i = 1; i < NWARP; i++) vi += aux[48 + i];
        atomicAdd(&g_viol, vi);
    }

    grid_bar(base + (++cnt) * NBLK);

    if (blk == 0 && tid == 0)
        out[0] = __ldcg(&g_viol) * (1.0f / (float)KTOK);
}

extern "C" void kernel_launch(void* const* d_in, const int* in_sizes, int n_in,
                              void* d_out, int out_size)
{
    (void)in_sizes; (void)n_in; (void)out_size;
    cudaFuncSetAttribute(traj_kernel,
                         cudaFuncAttributeMaxDynamicSharedMemorySize, SMEM_BYTES);
    const float *in = (const float *)d_in[0];
    float *out = (float *)d_out;
    traj_kernel<<<NBLK, NTHR, SMEM_BYTES>>>(in, out);
}

// round 6
// speedup vs baseline: 1.3125x; 1.3006x over previous
#include <cuda_runtime.h>
#include <math.h>

#define KTOK 2048
#define DDIM 2048
#define NBATCH 16
#define MAXIT 50
#define EPSF 1e-8f
#define STEPSZ (0.1f / 2048.0f)

#define NBLK 128
#define NTHR 256
#define NWARP 8
#define ROWS 16                 // tokens per CTA
#define RPW 2                   // rows per warp
#define DPT (DDIM / NTHR)       // 8 d-elements per thread
#define DSL (DDIM / NBLK)       // 16 d-elements per CTA slice
#define D4  (DDIM / 4)          // 512 float4
#define D4PT (D4 / NTHR)        // 2 float4 per thread

#define SMEM_FLOATS (ROWS * DDIM + DDIM + 32 + 64)
#define SMEM_BYTES (SMEM_FLOATS * 4)

// ---------------- global scratch (no allocations allowed) ----------------
__device__ __align__(16) float g_m[DDIM];
__device__ __align__(16) float g_grad[2][DDIM];
__device__ float g_slam[2];
__device__ float g_viol;
__device__ volatile unsigned g_flags[NBLK];
__device__ volatile unsigned g_gen;

// ---------------- grid barrier: flag array + single gen broadcast --------
__device__ __forceinline__ void grid_bar(unsigned phase)
{
    __syncthreads();
    __threadfence();                       // release
    if (blockIdx.x == 0) {
        if (threadIdx.x == 0) g_flags[0] = phase;
        if (threadIdx.x < NBLK) {
            while (g_flags[threadIdx.x] < phase) __nanosleep(64);
        }
        __syncthreads();
        if (threadIdx.x == 0) { __threadfence(); g_gen = phase; }
    } else {
        if (threadIdx.x == 0) {
            g_flags[blockIdx.x] = phase;
            while (g_gen < phase) __nanosleep(64);
        }
    }
    __syncthreads();
    __threadfence();                       // acquire
}

// deterministic block-wide sum: identical value on every thread & every CTA
__device__ __forceinline__ float block_sum(float v, float *red)
{
#pragma unroll
    for (int o = 16; o > 0; o >>= 1) v += __shfl_down_sync(0xffffffffu, v, o);
    __syncthreads();
    if ((threadIdx.x & 31) == 0) red[threadIdx.x >> 5] = v;
    __syncthreads();
    float s = red[0];
#pragma unroll
    for (int i = 1; i < NWARP; i++) s += red[i];
    __syncthreads();
    return s;
}

// log_map_at coefficients: v_k = -lam*p + mu*x_k, scalars only.
__device__ __forceinline__ void lam_mu(float dot, float xs, float p_sq,
                                       float &lam, float &mu)
{
    const float xy  = -dot;
    const float xsc = fminf(p_sq, 0.99f);
    const float ysc = fminf(xs, 0.99f);
    const float a   = 1.0f + 2.0f * xy + ysc;
    const float b   = 1.0f - xsc;
    const float den = fmaxf(1.0f + 2.0f * xy + xsc * ysc, EPSF);
    const float numsq = fmaxf(a * a * p_sq + b * b * xs - 2.0f * a * b * dot, 0.0f);
    const float rn  = sqrtf(numsq) / den;
    const float maxn = 1.0f - EPSF;
    const float c   = (rn >= maxn) ? (maxn - EPSF) / rn : 1.0f;
    const float n   = rn * c;
    const float s   = fminf(n, 1.0f - EPSF);
    const float scale = 2.0f * atanhf(s) / (n + EPSF);
    const float t   = (n < EPSF) ? 0.0f : scale * c / den;
    lam = t * a;
    mu  = t * b;
}

__global__ void __launch_bounds__(NTHR, 1)
traj_kernel(const float *__restrict__ in, float *__restrict__ out)
{
    extern __shared__ float smem[];
    float *Xs  = smem;                 // [ROWS][DDIM]
    float *Ps  = Xs + ROWS * DDIM;     // [DDIM] center, redundant per CTA
    float *red = Ps + DDIM;            // [32]
    float *aux = red + 32;             // [0..15]=xsq [16..31]=w0 [32..47]=mu [48..55]=warp scratch

    const int tid  = threadIdx.x;
    const int blk  = blockIdx.x;
    const int lane = tid & 31;
    const int w    = tid >> 5;
    const int ds   = blk * DSL;

    const unsigned base = g_gen;       // launch-relative phase baseline
    unsigned cnt = 0;

    // ---- zero global scratch slices ----
    if (tid < DSL) {
        g_m[ds + tid] = 0.0f;
        g_grad[0][ds + tid] = 0.0f;
        g_grad[1][ds + tid] = 0.0f;
    }
    if (blk == 0 && tid == 0) { g_viol = 0.0f; g_slam[0] = 0.0f; g_slam[1] = 0.0f; }

    // ---- load tokens: X[k,:] = mean_b in[k,b,:]; xsq per row ----
    const float inv_b = 1.0f / (float)NBATCH;
    for (int rr = 0; rr < RPW; rr++) {
        const int r = w * RPW + rr;
        const int k = blk * ROWS + r;
        const float4 *src = (const float4 *)(in + (size_t)k * NBATCH * DDIM);
        float4 *dst = (float4 *)(Xs + r * DDIM);
        float ss = 0.0f;
        for (int j = 0; j < DDIM / 128; j++) {
            const int d4 = lane + j * 32;
            float4 a = make_float4(0.f, 0.f, 0.f, 0.f);
#pragma unroll
            for (int b = 0; b < NBATCH; b++) {
                float4 t = src[b * D4 + d4];
                a.x += t.x; a.y += t.y; a.z += t.z; a.w += t.w;
            }
            a.x *= inv_b; a.y *= inv_b; a.z *= inv_b; a.w *= inv_b;
            dst[d4] = a;
            ss += a.x * a.x + a.y * a.y + a.z * a.z + a.w * a.w;
        }
#pragma unroll
        for (int o = 16; o > 0; o >>= 1) ss += __shfl_down_sync(0xffffffffu, ss, o);
        if (lane == 0) aux[r] = ss;
    }
    __syncthreads();

    // w0_k = log_map0 scale / K
    if (tid < ROWS) {
        const float xs = aux[tid];
        const float n  = sqrtf(xs);
        const float s  = fminf(n, 1.0f - EPSF);
        const float sc = (n < EPSF) ? 0.0f : atanhf(s) / (n + EPSF);
        aux[16 + tid] = sc * (1.0f / (float)KTOK);
    }
    __syncthreads();

    grid_bar(base + ++cnt);            // zeroing complete chip-wide

    // ---- m partial: g_m += sum_r w0_r * X[r,:] (vector RED) ----
    {
        const float4 *Xs4 = (const float4 *)Xs;
#pragma unroll
        for (int j = 0; j < D4PT; j++) {
            const int d4 = tid + j * NTHR;
            float4 acc = make_float4(0.f, 0.f, 0.f, 0.f);
#pragma unroll
            for (int r = 0; r < ROWS; r++) {
                const float wr = aux[16 + r];
                float4 x = Xs4[r * D4 + d4];
                acc.x += wr * x.x; acc.y += wr * x.y;
                acc.z += wr * x.z; acc.w += wr * x.w;
            }
            atomicAdd((float4 *)&g_m[4 * d4], acc);
        }
    }

    grid_bar(base + ++cnt);            // m complete

    // ---- p0 = exp_map0(m), redundant per CTA ----
    float p_sq;
    {
        float part = 0.0f, ml[DPT];
#pragma unroll
        for (int j = 0; j < DPT; j++) {
            ml[j] = __ldcg(&g_m[tid + j * NTHR]);
            part += ml[j] * ml[j];
        }
        const float msq = block_sum(part, red);
        const float n   = sqrtf(msq);
        const float sc  = (n < EPSF) ? 0.0f : tanhf(n) / (n + EPSF);
#pragma unroll
        for (int j = 0; j < DPT; j++) Ps[tid + j * NTHR] = sc * ml[j];
        p_sq = sc * sc * msq;
        __syncthreads();
    }

    // =================== Karcher loop ===================
    for (int it = 0; it < MAXIT; it++) {
        const int b = it & 1, nb = b ^ 1;

        // Phase 1: dots + lam/mu for own rows (scalar, as in 587us base)
        for (int rr = 0; rr < RPW; rr++) {
            const int r = w * RPW + rr;
            const float *xr = Xs + r * DDIM;
            float p2 = 0.0f;
            for (int j = 0; j < DDIM / 32; j++) {
                const int d = lane + j * 32;
                p2 += xr[d] * Ps[d];
            }
#pragma unroll
            for (int o = 16; o > 0; o >>= 1) p2 += __shfl_down_sync(0xffffffffu, p2, o);
            if (lane == 0) {
                float lam, mu;
                lam_mu(p2, aux[r], p_sq, lam, mu);
                aux[32 + r] = mu;
                if (rr == 0) aux[48 + w] = lam;
                else         aux[48 + w] += lam;
            }
        }
        __syncthreads();                // mu + lam partials visible
        if (tid == 0) {
            float sl = aux[48];
#pragma unroll
            for (int i = 1; i < NWARP; i++) sl += aux[48 + i];
            atomicAdd(&g_slam[b], sl);
        }

        // grad partial: vector RED, quarter the atomic ops
        {
            const float4 *Xs4 = (const float4 *)Xs;
#pragma unroll
            for (int j = 0; j < D4PT; j++) {
                const int d4 = tid + j * NTHR;
                float4 acc = make_float4(0.f, 0.f, 0.f, 0.f);
#pragma unroll
                for (int r = 0; r < ROWS; r++) {
                    const float mr = aux[32 + r];
                    float4 x = Xs4[r * D4 + d4];
                    acc.x += mr * x.x; acc.y += mr * x.y;
                    acc.z += mr * x.z; acc.w += mr * x.w;
                }
                atomicAdd((float4 *)&g_grad[b][4 * d4], acc);
            }
        }

        grid_bar(base + ++cnt);         // grad complete

        // Phase 2: redundant p update per CTA
        const float slam = __ldcg(&g_slam[b]);
        float gl[DPT], a1 = 0.0f, a2 = 0.0f;
#pragma unroll
        for (int j = 0; j < DPT; j++) {
            const int d = tid + j * NTHR;
            const float g = __ldcg(&g_grad[b][d]) - Ps[d] * slam;
            gl[j] = g;
            a1 += g * g;
            a2 += Ps[d] * g;
        }
        const float gg = block_sum(a1, red);
        const float pg = block_sum(a2, red);

        // zero next-iteration buffers (nb last read before previous barrier)
        if (tid < DSL) g_grad[nb][ds + tid] = 0.0f;
        if (blk == 0 && tid == 0) g_slam[nb] = 0.0f;

        const float n_v = STEPSZ * sqrtf(gg);
        if (n_v >= EPSF) {
            const float sc  = tanhf(0.5f * n_v) / (n_v + EPSF);
            const float xy  = -STEPSZ * sc * pg;
            const float ysq = STEPSZ * STEPSZ * sc * sc * gg;
            const float xsc = fminf(p_sq, 0.99f);
            const float ysc = fminf(ysq, 0.99f);
            const float A   = 1.0f + 2.0f * xy + ysc;
            const float B   = 1.0f - xsc;
            const float dn  = fmaxf(1.0f + 2.0f * xy + xsc * ysc, EPSF);
            const float ca  = A / dn;
            const float cb  = (-STEPSZ * sc) * B / dn;
            float pp = 0.0f;
#pragma unroll
            for (int j = 0; j < DPT; j++) {
                const int d = tid + j * NTHR;
                const float nv = ca * Ps[d] + cb * gl[j];
                Ps[d] = nv;
                pp += nv * nv;
            }
            float rsq = block_sum(pp, red);
            const float rn = sqrtf(rsq);
            if (rn >= 1.0f - EPSF) {
                const float cf = (1.0f - 2.0f * EPSF) / rn;
#pragma unroll
                for (int j = 0; j < DPT; j++) Ps[tid + j * NTHR] *= cf;
                rsq *= cf * cf;
            }
            p_sq = rsq;
        }
        __syncthreads();

        grid_bar(base + ++cnt);         // zeroing + update settled
    }

    // ---- final distances + violation ----
    float vi = 0.0f;
    for (int rr = 0; rr < RPW; rr++) {
        const int r = w * RPW + rr;
        const float *xr = Xs + r * DDIM;
        float p2 = 0.0f;
        for (int j = 0; j < DDIM / 32; j++) {
            const int d = lane + j * 32;
            p2 += xr[d] * Ps[d];
        }
#pragma unroll
        for (int o = 16; o > 0; o >>= 1) p2 += __shfl_down_sync(0xffffffffu, p2, o);
        if (lane == 0) {
            const float xs  = aux[r];
            const float dsq = xs - 2.0f * p2 + p_sq;
            const float den = fmaxf((1.0f - xs) * (1.0f - p_sq), EPSF);
            const float fr  = fmaxf(dsq / den, 0.0f);
            const float dd  = asinhf(sqrtf(fr));
            vi += fmaxf(dd - 2.0f, 0.0f);
        }
    }
    if (lane == 0) atomicAdd(&g_viol, vi);

    grid_bar(base + ++cnt);

    if (blk == 0 && tid == 0) out[0] = g_viol * (1.0f / (float)KTOK);
}

extern "C" void kernel_launch(void* const* d_in, const int* in_sizes, int n_in,
                              void* d_out, int out_size)
{
    (void)in_sizes; (void)n_in; (void)out_size;
    cudaFuncSetAttribute(traj_kernel,
                         cudaFuncAttributeMaxDynamicSharedMemorySize, SMEM_BYTES);
    const float *in = (const float *)d_in[0];
    float *out = (float *)d_out;
    traj_kernel<<<NBLK, NTHR, SMEM_BYTES>>>(in, out);
}